// round 6
// baseline (speedup 1.0000x reference)
#include <cuda_runtime.h>
#include <cuda_bf16.h>
#include <cstdint>

#define NN 100000
#define EE 1600000
#define NB_SCAN 98

typedef unsigned long long ull;

// ---------------- persistent device scratch ----------------
__device__ float g_h0[NN * 64];
__device__ float g_h1[NN * 64];
__device__ int   g_deg[NN];
__device__ int   g_off[NN + 1];
__device__ int   g_cur[NN];
__device__ int   g_srcs[EE];
__device__ int   g_bsum[NB_SCAN];

// ---------------- CSR build (unchanged, validated in R4) ----------------
__global__ void k_zero_deg() {
    int i = blockIdx.x * 256 + threadIdx.x;
    if (i < NN) g_deg[i] = 0;
}
__global__ void k_hist(const int* __restrict__ ei) {
    int e = blockIdx.x * 256 + threadIdx.x;
    if (e < EE) {
        int d = ei[EE + e];
        if (d >= 0 && d < NN) atomicAdd(&g_deg[d], 1);
    }
}
__global__ void k_scan1() {
    __shared__ int sh[1024];
    int t = threadIdx.x;
    int i = blockIdx.x * 1024 + t;
    int v = (i < NN) ? g_deg[i] : 0;
    sh[t] = v;
    __syncthreads();
    for (int d = 1; d < 1024; d <<= 1) {
        int a = (t >= d) ? sh[t - d] : 0;
        __syncthreads();
        sh[t] += a;
        __syncthreads();
    }
    if (i < NN) g_off[i] = sh[t] - v;
    if (t == 1023) g_bsum[blockIdx.x] = sh[1023];
}
__global__ void k_scan2() {
    int acc = 0;
    for (int b = 0; b < NB_SCAN; b++) { int t = g_bsum[b]; g_bsum[b] = acc; acc += t; }
}
__global__ void k_scanadd() {
    int i = blockIdx.x * 256 + threadIdx.x;
    if (i < NN) {
        int v = g_off[i] + g_bsum[i >> 10];
        g_off[i] = v;
        g_cur[i] = v;
    }
    if (i == 0) g_off[NN] = EE;
}
__global__ void k_scatter(const int* __restrict__ ei) {
    int e = blockIdx.x * 256 + threadIdx.x;
    if (e < EE) {
        int d = ei[EE + e];
        int s = ei[e];
        if (d >= 0 && d < NN && s >= 0 && s < NN) {
            int p = atomicAdd(&g_cur[d], 1);
            if (p < EE) g_srcs[p] = s;
        }
    }
}
__global__ void k_segsort() {
    int n = blockIdx.x * 256 + threadIdx.x;
    if (n >= NN) return;
    int a = g_off[n], b = g_off[n + 1];
    for (int i = a + 1; i < b; i++) {
        int key = g_srcs[i];
        int j = i - 1;
        while (j >= a && g_srcs[j] > key) { g_srcs[j + 1] = g_srcs[j]; j--; }
        g_srcs[j + 1] = key;
    }
}

// ---------------- packed f32x2 helpers ----------------
__device__ __forceinline__ void fma2(ull& d, ull a, ull b) {
    asm("fma.rn.f32x2 %0, %1, %2, %0;" : "+l"(d) : "l"(a), "l"(b));
}
__device__ __forceinline__ ull pack_dup(float v) {
    ull r;
    asm("mov.b64 %0, {%1, %1};" : "=l"(r) : "f"(v));
    return r;
}
__device__ __forceinline__ ull pack2(float lo, float hi) {
    ull r;
    asm("mov.b64 %0, {%1, %2};" : "=l"(r) : "f"(lo), "f"(hi));
    return r;
}
__device__ __forceinline__ void unpack2(ull v, float& lo, float& hi) {
    asm("mov.b64 {%0, %1}, %2;" : "=f"(lo), "=f"(hi) : "l"(v));
}

// Zt layout: feature-major [k][node], 64 x 128 words, XOR-swizzled on the node
// index so column writes (aggregation / epilogue1) don't all land on one bank.
// Low 3 bits of r untouched -> 8-node groups stay contiguous for packed a-loads.
__device__ __forceinline__ int zidx(int k, int r) {
    return k * 128 + (r ^ (((k >> 1) & 3) << 3));
}

// ---------------- fused GIN layer: aggregate + MLP + BN + ReLU ----------------
// 128 threads, 128 nodes/block. Static smem: Zt 32KB + Ws 16KB = 48KB exactly.
// GEMM: thread tile 8 rows x 8 cols, accumulators packed f32x2 over row pairs.
__global__ void __launch_bounds__(128) k_layer(
    const float* __restrict__ x, float* __restrict__ dout,
    const float* __restrict__ W1, const float* __restrict__ b1,
    const float* __restrict__ W2, const float* __restrict__ b2,
    const float* __restrict__ bng, const float* __restrict__ bnb,
    const float* __restrict__ bnm, const float* __restrict__ bnv,
    int layer)
{
    __shared__ __align__(16) float Zt[64 * 128];
    __shared__ __align__(16) float Ws[64 * 64];

    const float* hin  = (layer == 0) ? x    : ((layer & 1) ? g_h0 : g_h1);
    float*       hout = (layer == 4) ? dout : ((layer & 1) ? g_h1 : g_h0);
    const float* W1p = W1 + layer * 4096;
    const float* W2p = W2 + layer * 4096;

    int tid = threadIdx.x, wid = tid >> 5, lid = tid & 31;
    int base = blockIdx.x * 128;

    // W1 -> Ws (row k = input feat, col = output feat; matches GEMM b-loads)
    for (int i = tid; i < 4096; i += 128) Ws[i] = W1p[i];

    // ---- aggregation: warp per node; lane l accumulates feats {2l, 2l+1} ----
    for (int r = wid; r < 128; r += 4) {
        int n = base + r;
        float ax = 0.f, ay = 0.f;
        if (n < NN) {
            float2 self = *(const float2*)(hin + n * 64 + 2 * lid);
            ax = self.x; ay = self.y;
            int s0 = g_off[n], s1 = g_off[n + 1];
            for (int j0 = s0; j0 < s1; j0 += 32) {
                int myj = j0 + lid;
                int mys = (myj < s1) ? g_srcs[myj] : 0;
                int cnt = min(32, s1 - j0);
                for (int i = 0; i < cnt; i++) {
                    int s = __shfl_sync(0xffffffffu, mys, i);
                    float2 v = __ldg((const float2*)(hin + s * 64 + 2 * lid));
                    ax += v.x; ay += v.y;
                }
            }
        }
        Zt[zidx(2 * lid,     r)] = ax;
        Zt[zidx(2 * lid + 1, r)] = ay;
    }
    __syncthreads();

    // ---- GEMM1: acc[128x64] = Z @ W1 ----
    int tx = tid & 7;        // col group: cols 8tx..8tx+7
    int ty = tid >> 3;       // row group: rows 8ty..8ty+7
    ull A[4][8];             // [rowpair][col], packed (row 2p, row 2p+1)
    #pragma unroll
    for (int p = 0; p < 4; p++)
        #pragma unroll
        for (int j = 0; j < 8; j++) A[p][j] = 0ull;

    #pragma unroll 8
    for (int k = 0; k < 64; k++) {
        const float* za = Zt + zidx(k, 8 * ty);
        ulonglong2 aA = *(const ulonglong2*)za;          // rows (0,1),(2,3)
        ulonglong2 aB = *(const ulonglong2*)(za + 4);    // rows (4,5),(6,7)
        const float* wb = Ws + k * 64 + 8 * tx;
        float4 b0 = *(const float4*)wb;
        float4 b1v_ = *(const float4*)(wb + 4);
        ull bd[8];
        bd[0] = pack_dup(b0.x); bd[1] = pack_dup(b0.y);
        bd[2] = pack_dup(b0.z); bd[3] = pack_dup(b0.w);
        bd[4] = pack_dup(b1v_.x); bd[5] = pack_dup(b1v_.y);
        bd[6] = pack_dup(b1v_.z); bd[7] = pack_dup(b1v_.w);
        #pragma unroll
        for (int j = 0; j < 8; j++) {
            fma2(A[0][j], aA.x, bd[j]);
            fma2(A[1][j], aA.y, bd[j]);
            fma2(A[2][j], aB.x, bd[j]);
            fma2(A[3][j], aB.y, bd[j]);
        }
    }
    __syncthreads();         // everyone done reading Zt / Ws

    // ---- epilogue1: Y1 = relu(acc + b1) -> Zt (feat-major, swizzled); Ws <- W2 ----
    {
        float bv[8];
        #pragma unroll
        for (int j = 0; j < 8; j++) bv[j] = __ldg(&b1[layer * 64 + 8 * tx + j]);
        #pragma unroll
        for (int p = 0; p < 4; p++) {
            #pragma unroll
            for (int j = 0; j < 8; j++) {
                float lo, hi;
                unpack2(A[p][j], lo, hi);
                lo = fmaxf(lo + bv[j], 0.f);
                hi = fmaxf(hi + bv[j], 0.f);
                *(float2*)(Zt + zidx(8 * tx + j, 8 * ty + 2 * p)) = make_float2(lo, hi);
            }
        }
    }
    for (int i = tid; i < 4096; i += 128) Ws[i] = W2p[i];
    __syncthreads();

    // ---- GEMM2: acc = Y1 @ W2 ----
    #pragma unroll
    for (int p = 0; p < 4; p++)
        #pragma unroll
        for (int j = 0; j < 8; j++) A[p][j] = 0ull;

    #pragma unroll 8
    for (int k = 0; k < 64; k++) {
        const float* za = Zt + zidx(k, 8 * ty);
        ulonglong2 aA = *(const ulonglong2*)za;
        ulonglong2 aB = *(const ulonglong2*)(za + 4);
        const float* wb = Ws + k * 64 + 8 * tx;
        float4 b0 = *(const float4*)wb;
        float4 b1v_ = *(const float4*)(wb + 4);
        ull bd[8];
        bd[0] = pack_dup(b0.x); bd[1] = pack_dup(b0.y);
        bd[2] = pack_dup(b0.z); bd[3] = pack_dup(b0.w);
        bd[4] = pack_dup(b1v_.x); bd[5] = pack_dup(b1v_.y);
        bd[6] = pack_dup(b1v_.z); bd[7] = pack_dup(b1v_.w);
        #pragma unroll
        for (int j = 0; j < 8; j++) {
            fma2(A[0][j], aA.x, bd[j]);
            fma2(A[1][j], aA.y, bd[j]);
            fma2(A[2][j], aB.x, bd[j]);
            fma2(A[3][j], aB.y, bd[j]);
        }
    }

    // ---- epilogue2: O = acc + b2, BN(eval)+ReLU for layers 0-3, store ----
    {
        float b2v[8], scv[8], shv[8];
        #pragma unroll
        for (int j = 0; j < 8; j++) {
            int c = layer * 64 + 8 * tx + j;
            b2v[j] = __ldg(&b2[c]);
            if (layer < 4) {
                float sc = __ldg(&bng[c]) * rsqrtf(__ldg(&bnv[c]) + 1e-5f);
                scv[j] = sc;
                shv[j] = __ldg(&bnb[c]) - __ldg(&bnm[c]) * sc;
            }
        }
        #pragma unroll
        for (int p = 0; p < 4; p++) {
            float r0[8], r1[8];
            #pragma unroll
            for (int j = 0; j < 8; j++) {
                float lo, hi;
                unpack2(A[p][j], lo, hi);
                lo += b2v[j]; hi += b2v[j];
                if (layer < 4) {
                    lo = fmaxf(lo * scv[j] + shv[j], 0.f);
                    hi = fmaxf(hi * scv[j] + shv[j], 0.f);
                }
                r0[j] = lo; r1[j] = hi;
            }
            int n0 = base + 8 * ty + 2 * p;
            if (n0 < NN) {
                *(float4*)(hout + n0 * 64 + 8 * tx)     = make_float4(r0[0], r0[1], r0[2], r0[3]);
                *(float4*)(hout + n0 * 64 + 8 * tx + 4) = make_float4(r0[4], r0[5], r0[6], r0[7]);
            }
            if (n0 + 1 < NN) {
                *(float4*)(hout + (n0 + 1) * 64 + 8 * tx)     = make_float4(r1[0], r1[1], r1[2], r1[3]);
                *(float4*)(hout + (n0 + 1) * 64 + 8 * tx + 4) = make_float4(r1[4], r1[5], r1[6], r1[7]);
            }
        }
    }
}

// ---------------- launch ----------------
extern "C" void kernel_launch(void* const* d_in, const int* in_sizes, int n_in,
                              void* d_out, int out_size) {
    const float* x   = (const float*)d_in[0];
    const int*   ei  = (const int*)d_in[1];     // [2, E] int32
    const float* W1  = (const float*)d_in[2];
    const float* b1  = (const float*)d_in[3];
    const float* W2  = (const float*)d_in[4];
    const float* b2  = (const float*)d_in[5];
    const float* bng = (const float*)d_in[6];
    const float* bnb = (const float*)d_in[7];
    const float* bnm = (const float*)d_in[8];
    const float* bnv = (const float*)d_in[9];
    float* out = (float*)d_out;

    const int gN = (NN + 255) / 256;
    const int gE = (EE + 255) / 256;

    k_zero_deg<<<gN, 256>>>();
    k_hist<<<gE, 256>>>(ei);
    k_scan1<<<NB_SCAN, 1024>>>();
    k_scan2<<<1, 1>>>();
    k_scanadd<<<gN, 256>>>();
    k_scatter<<<gE, 256>>>(ei);
    k_segsort<<<gN, 256>>>();

    const int gL = (NN + 127) / 128;     // 782
    for (int layer = 0; layer < 5; layer++) {
        k_layer<<<gL, 128>>>(x, out, W1, b1, W2, b2, bng, bnb, bnm, bnv, layer);
    }
}

// round 7
// speedup vs baseline: 1.6792x; 1.6792x over previous
#include <cuda_runtime.h>
#include <cuda_bf16.h>
#include <cstdint>

#define NN 100000
#define EE 1600000
#define NB_SCAN 98
#define PAD 68              // row stride (words) for shared tiles, 16B-aligned rows

typedef unsigned long long ull;

// ---------------- persistent device scratch ----------------
__device__ float g_h0[NN * 64];
__device__ float g_h1[NN * 64];
__device__ int   g_deg[NN];          // zero-initialized at load; re-zeroed by k_segsort each call
__device__ int   g_off[NN + 1];
__device__ int   g_cur[NN];
__device__ int   g_srcs[EE];
__device__ int   g_bsum[NB_SCAN];

// ---------------- CSR build ----------------
__global__ void k_hist(const int* __restrict__ ei) {
    int e = blockIdx.x * 256 + threadIdx.x;
    if (e < EE) {
        int d = ei[EE + e];
        if (d >= 0 && d < NN) atomicAdd(&g_deg[d], 1);
    }
}
__global__ void k_scan1() {
    __shared__ int sh[1024];
    int t = threadIdx.x;
    int i = blockIdx.x * 1024 + t;
    int v = (i < NN) ? g_deg[i] : 0;
    sh[t] = v;
    __syncthreads();
    for (int d = 1; d < 1024; d <<= 1) {
        int a = (t >= d) ? sh[t - d] : 0;
        __syncthreads();
        sh[t] += a;
        __syncthreads();
    }
    if (i < NN) g_off[i] = sh[t] - v;          // exclusive within block
    if (t == 1023) g_bsum[blockIdx.x] = sh[1023];
}
// scanadd with scan2 folded in: each block prefixes the (<=98) block sums itself.
__global__ void k_scanadd() {
    __shared__ int pref;
    int i = blockIdx.x * 256 + threadIdx.x;
    if (threadIdx.x == 0) {
        int g = blockIdx.x >> 2;               // (blockIdx.x*256)>>10, constant per block
        int acc = 0;
        for (int b = 0; b < g; b++) acc += g_bsum[b];
        pref = acc;
    }
    __syncthreads();
    if (i < NN) {
        int v = g_off[i] + pref;
        g_off[i] = v;
        g_cur[i] = v;
    }
    if (i == 0) g_off[NN] = EE;
}
__global__ void k_scatter(const int* __restrict__ ei) {
    int e = blockIdx.x * 256 + threadIdx.x;
    if (e < EE) {
        int d = ei[EE + e];
        int s = ei[e];
        if (d >= 0 && d < NN && s >= 0 && s < NN) {
            int p = atomicAdd(&g_cur[d], 1);
            if (p < EE) g_srcs[p] = s;
        }
    }
}
// Sort each node's src list (deterministic accumulation order) + re-zero g_deg
// for the next call (device globals start zeroed, so every call sees zeros).
__global__ void k_segsort() {
    int n = blockIdx.x * 256 + threadIdx.x;
    if (n >= NN) return;
    int a = g_off[n], b = g_off[n + 1];
    for (int i = a + 1; i < b; i++) {
        int key = g_srcs[i];
        int j = i - 1;
        while (j >= a && g_srcs[j] > key) { g_srcs[j + 1] = g_srcs[j]; j--; }
        g_srcs[j + 1] = key;
    }
    g_deg[n] = 0;
}

// ---------------- packed f32x2 helpers ----------------
__device__ __forceinline__ void fma2(ull& d, ull a, ull b) {
    asm("fma.rn.f32x2 %0, %1, %2, %0;" : "+l"(d) : "l"(a), "l"(b));
}
__device__ __forceinline__ ull pack_dup(float v) {
    ull r;
    asm("mov.b64 %0, {%1, %1};" : "=l"(r) : "f"(v));
    return r;
}
__device__ __forceinline__ ull pack2(float lo, float hi) {
    ull r;
    asm("mov.b64 %0, {%1, %2};" : "=l"(r) : "f"(lo), "f"(hi));
    return r;
}
__device__ __forceinline__ void unpack2(ull v, float& lo, float& hi) {
    asm("mov.b64 {%0, %1}, %2;" : "=f"(lo), "=f"(hi) : "l"(v));
}

// ---------------- fused GIN layer (R4 skeleton + f32x2 GEMM + float2 gather) ----------------
// 256 threads, 64 nodes/block. Zt: phase1 feature-major z, phase2 row-major Y1.
__global__ void __launch_bounds__(256) k_layer(
    const float* __restrict__ x, float* __restrict__ dout,
    const float* __restrict__ W1, const float* __restrict__ b1,
    const float* __restrict__ W2, const float* __restrict__ b2,
    const float* __restrict__ bng, const float* __restrict__ bnb,
    const float* __restrict__ bnm, const float* __restrict__ bnv,
    int layer)
{
    __shared__ __align__(16) float Zt[64 * PAD];
    __shared__ __align__(16) float Ws[64 * 64];
    __shared__ float bias1[64], bias2[64], bnsc[64], bnsh[64];

    const float* hin  = (layer == 0) ? x    : ((layer & 1) ? g_h0 : g_h1);
    float*       hout = (layer == 4) ? dout : ((layer & 1) ? g_h1 : g_h0);
    const float* W1p = W1 + layer * 4096;
    const float* W2p = W2 + layer * 4096;

    int tid = threadIdx.x;

    for (int i = tid; i < 4096; i += 256) Ws[i] = W1p[i];
    if (tid < 64) {
        bias1[tid] = b1[layer * 64 + tid];
        bias2[tid] = b2[layer * 64 + tid];
        if (layer < 4) {
            float sc  = bng[layer * 64 + tid] * rsqrtf(bnv[layer * 64 + tid] + 1e-5f);
            bnsc[tid] = sc;
            bnsh[tid] = bnb[layer * 64 + tid] - bnm[layer * 64 + tid] * sc;
        }
    }

    // ---- aggregation: warp per node; lane l -> feats {2l, 2l+1} (LDG.64/edge) ----
    int w = tid >> 5, l = tid & 31;
    int base = blockIdx.x * 64;
    for (int r = w; r < 64; r += 8) {
        int n = base + r;
        float ax = 0.f, ay = 0.f;
        if (n < NN) {
            float2 self = *(const float2*)(hin + n * 64 + 2 * l);
            ax = self.x; ay = self.y;
            int s0 = g_off[n], s1 = g_off[n + 1];
            #pragma unroll 4
            for (int j = s0; j < s1; j++) {
                int s = g_srcs[j];
                float2 v = __ldg((const float2*)(hin + s * 64 + 2 * l));
                ax += v.x; ay += v.y;
            }
        }
        Zt[(2 * l) * PAD + r]     = ax;       // z transposed: Zt[feat][node]
        Zt[(2 * l + 1) * PAD + r] = ay;
    }
    __syncthreads();

    // ---- GEMM1: Y1 = relu(Z @ W1 + b1), f32x2 accumulators ----
    int tx = tid & 15, ty = tid >> 4;         // 16x16 threads, 4x4 outputs each
    ull acc[2][4];                            // [rowpair p: rows (2p,2p+1)][col j]
    #pragma unroll
    for (int p = 0; p < 2; p++)
        #pragma unroll
        for (int j = 0; j < 4; j++) acc[p][j] = 0ull;

    #pragma unroll 8
    for (int k = 0; k < 64; k++) {
        float4 a = *(const float4*)(Zt + k * PAD + 4 * ty);   // rows 4ty..4ty+3 at feat k
        ull a01 = pack2(a.x, a.y), a23 = pack2(a.z, a.w);
        float4 b = *(const float4*)(Ws + k * 64 + 4 * tx);    // cols 4tx..4tx+3 at feat k
        ull b0 = pack_dup(b.x), b1d = pack_dup(b.y), b2d = pack_dup(b.z), b3d = pack_dup(b.w);
        fma2(acc[0][0], a01, b0); fma2(acc[0][1], a01, b1d);
        fma2(acc[0][2], a01, b2d); fma2(acc[0][3], a01, b3d);
        fma2(acc[1][0], a23, b0); fma2(acc[1][1], a23, b1d);
        fma2(acc[1][2], a23, b2d); fma2(acc[1][3], a23, b3d);
    }

    float y[4][4];
    #pragma unroll
    for (int p = 0; p < 2; p++)
        #pragma unroll
        for (int j = 0; j < 4; j++) {
            float lo, hi;
            unpack2(acc[p][j], lo, hi);
            y[2 * p][j]     = fmaxf(lo + bias1[4 * tx + j], 0.f);
            y[2 * p + 1][j] = fmaxf(hi + bias1[4 * tx + j], 0.f);
        }

    __syncthreads();

    // write Y1 row-major [node][feat] + reload W2
    #pragma unroll
    for (int i = 0; i < 4; i++) {
        *(float4*)(Zt + (4 * ty + i) * PAD + 4 * tx) =
            make_float4(y[i][0], y[i][1], y[i][2], y[i][3]);
    }
    for (int i = tid; i < 4096; i += 256) Ws[i] = W2p[i];
    __syncthreads();

    // ---- GEMM2: O = Y1 @ W2 + b2 ----
    #pragma unroll
    for (int p = 0; p < 2; p++)
        #pragma unroll
        for (int j = 0; j < 4; j++) acc[p][j] = 0ull;

    #pragma unroll 8
    for (int k = 0; k < 64; k++) {
        float4 b = *(const float4*)(Ws + k * 64 + 4 * tx);
        ull b0 = pack_dup(b.x), b1d = pack_dup(b.y), b2d = pack_dup(b.z), b3d = pack_dup(b.w);
        float a0 = Zt[(4 * ty + 0) * PAD + k];
        float a1 = Zt[(4 * ty + 1) * PAD + k];
        float a2 = Zt[(4 * ty + 2) * PAD + k];
        float a3 = Zt[(4 * ty + 3) * PAD + k];
        ull a01 = pack2(a0, a1), a23 = pack2(a2, a3);
        fma2(acc[0][0], a01, b0); fma2(acc[0][1], a01, b1d);
        fma2(acc[0][2], a01, b2d); fma2(acc[0][3], a01, b3d);
        fma2(acc[1][0], a23, b0); fma2(acc[1][1], a23, b1d);
        fma2(acc[1][2], a23, b2d); fma2(acc[1][3], a23, b3d);
    }

    // ---- epilogue: bias, optional BN(eval)+ReLU, store ----
    #pragma unroll
    for (int p = 0; p < 2; p++) {
        float r0[4], r1[4];
        #pragma unroll
        for (int j = 0; j < 4; j++) {
            float lo, hi;
            unpack2(acc[p][j], lo, hi);
            lo += bias2[4 * tx + j];
            hi += bias2[4 * tx + j];
            if (layer < 4) {
                lo = fmaxf(lo * bnsc[4 * tx + j] + bnsh[4 * tx + j], 0.f);
                hi = fmaxf(hi * bnsc[4 * tx + j] + bnsh[4 * tx + j], 0.f);
            }
            r0[j] = lo; r1[j] = hi;
        }
        int n0 = base + 4 * ty + 2 * p;
        if (n0 < NN)
            *(float4*)(hout + n0 * 64 + 4 * tx) = make_float4(r0[0], r0[1], r0[2], r0[3]);
        if (n0 + 1 < NN)
            *(float4*)(hout + (n0 + 1) * 64 + 4 * tx) = make_float4(r1[0], r1[1], r1[2], r1[3]);
    }
}

// ---------------- launch ----------------
extern "C" void kernel_launch(void* const* d_in, const int* in_sizes, int n_in,
                              void* d_out, int out_size) {
    const float* x   = (const float*)d_in[0];
    const int*   ei  = (const int*)d_in[1];     // [2, E] int32
    const float* W1  = (const float*)d_in[2];
    const float* b1  = (const float*)d_in[3];
    const float* W2  = (const float*)d_in[4];
    const float* b2  = (const float*)d_in[5];
    const float* bng = (const float*)d_in[6];
    const float* bnb = (const float*)d_in[7];
    const float* bnm = (const float*)d_in[8];
    const float* bnv = (const float*)d_in[9];
    float* out = (float*)d_out;

    const int gN = (NN + 255) / 256;     // 391
    const int gE = (EE + 255) / 256;     // 6250

    // CSR build (g_deg arrives zeroed: zero-init at load, re-zeroed by k_segsort)
    k_hist<<<gE, 256>>>(ei);             // launch 0
    k_scan1<<<NB_SCAN, 1024>>>();        // launch 1
    k_scanadd<<<gN, 256>>>();            // launch 2 (scan2 folded in)
    k_scatter<<<gE, 256>>>(ei);          // launch 3
    k_segsort<<<gN, 256>>>();            // launch 4 (+ g_deg re-zero)

    // 5 fused layers; launch 5 = layer 0 (ncu -s 5 lands here)
    const int gL = (NN + 63) / 64;       // 1563
    for (int layer = 0; layer < 5; layer++) {
        k_layer<<<gL, 256>>>(x, out, W1, b1, W2, b2, bng, bnb, bnm, bnv, layer);
    }
}